// round 8
// baseline (speedup 1.0000x reference)
#include <cuda_runtime.h>
#include <cuda_bf16.h>
#include <cstdint>

// Problem constants
#define BB 2
#define LL 2048
#define DD 2048
#define HH 16
#define HD 128
#define TT (BB*LL)            // 4096 tokens
#define QKVN (3*DD)           // 6144
#define OUT_ELEMS ((long)TT*DD)          // 8388608
#define SCORE_ELEMS ((long)BB*HH*LL*LL)  // 134217728

// Scratch (device globals; no allocation allowed)
__device__ float g_xn[TT*DD];
__device__ float g_qkv[TT*QKVN];
__device__ float g_attn[TT*DD];
__device__ float g_after[TT*DD];
__device__ float g_yn[TT*DD];
__device__ float g_hidden[TT*DD];
__device__ float g_hg[TT*DD];
// tf32-rounded weight copies
__device__ float g_wqkv_t[(long)QKVN*DD];
__device__ float g_wout_t[(long)DD*DD];
__device__ float g_win_t[(long)DD*DD];
__device__ float g_whid_t[(long)DD*DD];
__device__ float g_wgate_t[(long)DD*DD];

__device__ __forceinline__ uint32_t f2tf32(float f) {
    uint32_t u;
    asm("cvt.rna.tf32.f32 %0, %1;" : "=r"(u) : "f"(f));
    return u;
}
__device__ __forceinline__ float round_tf32(float f) {
    return __uint_as_float(f2tf32(f));
}

// ---------------------------------------------------------------------------
// Weight pre-conversion: fp32 -> tf32-rounded fp32 bits
// ---------------------------------------------------------------------------
__global__ void cvt_tf32_kernel(const float* __restrict__ src,
                                float* __restrict__ dst, int n4) {
    int i = blockIdx.x * blockDim.x + threadIdx.x;
    if (i < n4) {
        float4 v = ((const float4*)src)[i];
        v.x = round_tf32(v.x); v.y = round_tf32(v.y);
        v.z = round_tf32(v.z); v.w = round_tf32(v.w);
        ((float4*)dst)[i] = v;
    }
}

// ---------------------------------------------------------------------------
// Block reductions (256 threads = 8 warps)
// ---------------------------------------------------------------------------
__device__ __forceinline__ float block_reduce_max(float v, float* red) {
    int lane = threadIdx.x & 31, wid = threadIdx.x >> 5;
    #pragma unroll
    for (int o = 16; o; o >>= 1) v = fmaxf(v, __shfl_xor_sync(0xffffffffu, v, o));
    if (lane == 0) red[wid] = v;
    __syncthreads();
    if (wid == 0) {
        float u = (lane < 8) ? red[lane] : -3.4e38f;
        #pragma unroll
        for (int o = 4; o; o >>= 1) u = fmaxf(u, __shfl_xor_sync(0xffffffffu, u, o));
        if (lane == 0) red[0] = u;
    }
    __syncthreads();
    float r = red[0];
    __syncthreads();
    return r;
}

__device__ __forceinline__ float block_reduce_sum(float v, float* red) {
    int lane = threadIdx.x & 31, wid = threadIdx.x >> 5;
    #pragma unroll
    for (int o = 16; o; o >>= 1) v += __shfl_xor_sync(0xffffffffu, v, o);
    if (lane == 0) red[wid] = v;
    __syncthreads();
    if (wid == 0) {
        float u = (lane < 8) ? red[lane] : 0.f;
        #pragma unroll
        for (int o = 4; o; o >>= 1) u += __shfl_xor_sync(0xffffffffu, u, o);
        if (lane == 0) red[0] = u;
    }
    __syncthreads();
    float r = red[0];
    __syncthreads();
    return r;
}

// ---------------------------------------------------------------------------
// RMSNorm: one block per token row of D=2048; output tf32-rounded
// ---------------------------------------------------------------------------
__global__ void rmsnorm_kernel(const float* __restrict__ x,
                               const float* __restrict__ g,
                               float* __restrict__ y) {
    __shared__ float red[32];
    long row = blockIdx.x;
    const float* xr = x + row * DD;
    float* yr = y + row * DD;
    int tid = threadIdx.x;

    float4 v0 = *(const float4*)&xr[tid * 4];
    float4 v1 = *(const float4*)&xr[1024 + tid * 4];
    float ss = v0.x*v0.x + v0.y*v0.y + v0.z*v0.z + v0.w*v0.w
             + v1.x*v1.x + v1.y*v1.y + v1.z*v1.z + v1.w*v1.w;
    ss = block_reduce_sum(ss, red);
    float norm = rsqrtf(ss * (1.0f / DD) + 1e-6f);

    float4 g0 = *(const float4*)&g[tid * 4];
    float4 g1 = *(const float4*)&g[1024 + tid * 4];
    float4 o0, o1;
    o0.x = round_tf32(v0.x * norm * g0.x); o0.y = round_tf32(v0.y * norm * g0.y);
    o0.z = round_tf32(v0.z * norm * g0.z); o0.w = round_tf32(v0.w * norm * g0.w);
    o1.x = round_tf32(v1.x * norm * g1.x); o1.y = round_tf32(v1.y * norm * g1.y);
    o1.z = round_tf32(v1.z * norm * g1.z); o1.w = round_tf32(v1.w * norm * g1.w);
    *(float4*)&yr[tid * 4] = o0;
    *(float4*)&yr[1024 + tid * 4] = o1;
}

// ---------------------------------------------------------------------------
// Row softmax over rows of length L=2048 (DRAM roofline; output fp32)
// ---------------------------------------------------------------------------
__global__ void softmax_kernel(float* __restrict__ S) {
    __shared__ float red[32];
    long row = blockIdx.x;
    float* p = S + row * (long)LL;
    int tid = threadIdx.x;

    float4 v0 = *(const float4*)&p[tid * 4];
    float4 v1 = *(const float4*)&p[1024 + tid * 4];
    float m = fmaxf(fmaxf(fmaxf(v0.x, v0.y), fmaxf(v0.z, v0.w)),
                    fmaxf(fmaxf(v1.x, v1.y), fmaxf(v1.z, v1.w)));
    m = block_reduce_max(m, red);

    v0.x = __expf(v0.x - m); v0.y = __expf(v0.y - m);
    v0.z = __expf(v0.z - m); v0.w = __expf(v0.w - m);
    v1.x = __expf(v1.x - m); v1.y = __expf(v1.y - m);
    v1.z = __expf(v1.z - m); v1.w = __expf(v1.w - m);

    float s = v0.x + v0.y + v0.z + v0.w + v1.x + v1.y + v1.z + v1.w;
    s = block_reduce_sum(s, red);
    float inv = 1.0f / s;

    v0.x *= inv; v0.y *= inv; v0.z *= inv; v0.w *= inv;
    v1.x *= inv; v1.y *= inv; v1.z *= inv; v1.w *= inv;
    *(float4*)&p[tid * 4] = v0;
    *(float4*)&p[1024 + tid * 4] = v1;
}

// ---------------------------------------------------------------------------
// TF32 tensor-core GEMM, CTA tile 256x128x32, 8 warps (4x2), warp tile 64x64.
// 3-stage cp.async pipeline; ldmatrix.x4 fragment loads.
//   TB=true : C = epi( A[M,K] * W[N,K]^T )   (NT, both K-major)
//   TB=false: C = epi( A[M,K] * B[K,N] )     (NN; B frag loads scalar)
// ---------------------------------------------------------------------------
__device__ __forceinline__ void cp16(float* smem_dst, const float* gmem_src) {
    uint32_t d = (uint32_t)__cvta_generic_to_shared(smem_dst);
    asm volatile("cp.async.cg.shared.global [%0], [%1], 16;\n"
                 :: "r"(d), "l"(gmem_src));
}

__device__ __forceinline__ void ldsm_x4(uint32_t& r0, uint32_t& r1,
                                        uint32_t& r2, uint32_t& r3,
                                        const float* p) {
    uint32_t a = (uint32_t)__cvta_generic_to_shared(p);
    asm volatile("ldmatrix.sync.aligned.m8n8.x4.shared.b16 {%0,%1,%2,%3}, [%4];"
                 : "=r"(r0), "=r"(r1), "=r"(r2), "=r"(r3) : "r"(a));
}

__device__ __forceinline__ void mma_tf32(float* c, uint32_t a0, uint32_t a1,
                                         uint32_t a2, uint32_t a3,
                                         uint32_t b0, uint32_t b1) {
    asm volatile(
        "mma.sync.aligned.m16n8k8.row.col.f32.tf32.tf32.f32 "
        "{%0,%1,%2,%3}, {%4,%5,%6,%7}, {%8,%9}, {%0,%1,%2,%3};"
        : "+f"(c[0]), "+f"(c[1]), "+f"(c[2]), "+f"(c[3])
        : "r"(a0), "r"(a1), "r"(a2), "r"(a3), "r"(b0), "r"(b1));
}

template<bool TB, bool CVTA, bool ROUNDC>
__global__ __launch_bounds__(256, 1)
void gemm_tc(const float* __restrict__ A, const float* __restrict__ Bm,
             float* __restrict__ C,
             int K, int lda, int ldb, int ldc,
             int zH,
             long sAb, long sAh, long sBb, long sBh, long sCb, long sCh,
             float scale,
             const float* __restrict__ mulp,
             const float* __restrict__ addp,
             int relu) {
    constexpr int PA = 36;                     // floats per row (k-major rows)
    constexpr int ASZ = 256 * PA;              // one A buffer (256 m-rows)
    constexpr int PBNN = 136;                  // floats per B row (k-major, NN)
    constexpr int BSZ = TB ? 128 * PA : 32 * PBNN;

    extern __shared__ float smem[];
    float* As = smem;                  // 3 buffers
    float* Bs = smem + 3 * ASZ;        // 3 buffers

    int z = blockIdx.z;
    int zb = z / zH, zh = z % zH;
    A  += zb * sAb + zh * sAh;
    Bm += zb * sBb + zh * sBh;
    C  += zb * sCb + zh * sCh;
    const float* mp = mulp ? (mulp + zb * sCb + zh * sCh) : nullptr;
    const float* ap = addp ? (addp + zb * sCb + zh * sCh) : nullptr;

    int tid = threadIdx.x;
    int lane = tid & 31, warp = tid >> 5;
    int wm = warp >> 1;         // 0..3
    int wn = warp & 1;          // 0..1
    int g = lane >> 2, tig = lane & 3;
    int m_base = wm * 64, n_base = wn * 64;
    int row0 = blockIdx.y * 256;
    int col0 = blockIdx.x * 128;

    // ldmatrix per-lane address components (mat = lane>>3):
    //   row_in_tile = (mat&1)*8 + (lane&7), col_ofs = (mat>>1)*4
    int lm_r = ((lane >> 3) & 1) * 8 + (lane & 7);
    int lm_c = ((lane >> 4) & 1) * 4;

    float acc[4][8][4];
    #pragma unroll
    for (int mi = 0; mi < 4; mi++)
        #pragma unroll
        for (int ni = 0; ni < 8; ni++)
            #pragma unroll
            for (int r = 0; r < 4; r++) acc[mi][ni][r] = 0.f;

    int ar = tid >> 3;              // 0..31: row group
    int akq = (tid & 7) * 4;        // k offset within 32

    auto issue_tile = [&](int k0, int buf) {
        float* Ab = As + buf * ASZ;
        #pragma unroll
        for (int t = 0; t < 8; t++) {
            int r = ar + t * 32;
            cp16(&Ab[r * PA + akq], &A[(long)(row0 + r) * lda + k0 + akq]);
        }
        float* Bb = Bs + buf * BSZ;
        if (TB) {
            #pragma unroll
            for (int t = 0; t < 4; t++) {
                int r = ar + t * 32;
                cp16(&Bb[r * PA + akq], &Bm[(long)(col0 + r) * ldb + k0 + akq]);
            }
        } else {
            #pragma unroll
            for (int t = 0; t < 4; t++) {
                int q = tid + t * 256;
                int r = q >> 5;             // k row 0..31
                int c = (q & 31) * 4;       // col 0..124
                cp16(&Bb[r * PBNN + c], &Bm[(long)(k0 + r) * ldb + col0 + c]);
            }
        }
        asm volatile("cp.async.commit_group;\n" ::);
    };

    int nk = K >> 5;
    issue_tile(0, 0);
    if (nk > 1) issue_tile(32, 1);

    for (int i = 0; i < nk; i++) {
        if (i + 1 < nk) {
            asm volatile("cp.async.wait_group 1;\n" ::);
        } else {
            asm volatile("cp.async.wait_group 0;\n" ::);
        }
        __syncthreads();
        if (i + 2 < nk) issue_tile((i + 2) << 5, (i + 2) % 3);

        const float* Ab = As + (i % 3) * ASZ;
        const float* Bb = Bs + (i % 3) * BSZ;

        #pragma unroll
        for (int kk = 0; kk < 32; kk += 8) {
            uint32_t af[4][4], bf[8][2];
            #pragma unroll
            for (int mi = 0; mi < 4; mi++) {
                const float* p = Ab + (m_base + mi * 16 + lm_r) * PA + kk + lm_c;
                ldsm_x4(af[mi][0], af[mi][1], af[mi][2], af[mi][3], p);
                if (CVTA) {
                    af[mi][0] = f2tf32(__uint_as_float(af[mi][0]));
                    af[mi][1] = f2tf32(__uint_as_float(af[mi][1]));
                    af[mi][2] = f2tf32(__uint_as_float(af[mi][2]));
                    af[mi][3] = f2tf32(__uint_as_float(af[mi][3]));
                }
            }
            if (TB) {
                #pragma unroll
                for (int p2 = 0; p2 < 4; p2++) {
                    const float* p = Bb + (n_base + p2 * 16 + lm_r) * PA + kk + lm_c;
                    ldsm_x4(bf[2 * p2][0], bf[2 * p2 + 1][0],
                            bf[2 * p2][1], bf[2 * p2 + 1][1], p);
                }
            } else {
                #pragma unroll
                for (int ni = 0; ni < 8; ni++) {
                    int nc = n_base + ni * 8 + g;
                    bf[ni][0] = __float_as_uint(Bb[(kk + tig) * PBNN + nc]);
                    bf[ni][1] = __float_as_uint(Bb[(kk + tig + 4) * PBNN + nc]);
                }
            }
            #pragma unroll
            for (int mi = 0; mi < 4; mi++)
                #pragma unroll
                for (int ni = 0; ni < 8; ni++)
                    mma_tf32(acc[mi][ni], af[mi][0], af[mi][1], af[mi][2],
                             af[mi][3], bf[ni][0], bf[ni][1]);
        }
        __syncthreads();
    }

    // --- epilogue ---
    #pragma unroll
    for (int mi = 0; mi < 4; mi++) {
        #pragma unroll
        for (int half = 0; half < 2; half++) {
            int r = row0 + m_base + mi * 16 + g + half * 8;
            #pragma unroll
            for (int ni = 0; ni < 8; ni++) {
                int c = col0 + n_base + ni * 8 + tig * 2;
                long idx = (long)r * ldc + c;
                float2 v;
                v.x = acc[mi][ni][half * 2 + 0] * scale;
                v.y = acc[mi][ni][half * 2 + 1] * scale;
                if (mp) {
                    float2 m2 = *(const float2*)&mp[idx];
                    v.x *= m2.x; v.y *= m2.y;
                }
                if (relu) { v.x = fmaxf(v.x, 0.f); v.y = fmaxf(v.y, 0.f); }
                if (ap) {
                    float2 a2 = *(const float2*)&ap[idx];
                    v.x += a2.x; v.y += a2.y;
                }
                if (ROUNDC) { v.x = round_tf32(v.x); v.y = round_tf32(v.y); }
                *(float2*)&C[idx] = v;
            }
        }
    }
}

// ---------------------------------------------------------------------------
extern "C" void kernel_launch(void* const* d_in, const int* in_sizes, int n_in,
                              void* d_out, int out_size) {
    (void)in_sizes; (void)n_in; (void)out_size;
    const float* x       = (const float*)d_in[0];
    const float* w_qkv   = (const float*)d_in[1];
    const float* w_out   = (const float*)d_in[2];
    const float* w_in    = (const float*)d_in[3];
    const float* w_hid   = (const float*)d_in[4];
    const float* w_gate  = (const float*)d_in[5];
    const float* g_attng = (const float*)d_in[6];
    const float* g_ffng  = (const float*)d_in[7];
    float* out = (float*)d_out;
    float* scores = out + OUT_ELEMS;

    float *p_xn, *p_qkv, *p_attn, *p_after, *p_yn, *p_hidden, *p_hg;
    float *p_wqkv, *p_wout, *p_win, *p_whid, *p_wgate;
    cudaGetSymbolAddress((void**)&p_xn, g_xn);
    cudaGetSymbolAddress((void**)&p_qkv, g_qkv);
    cudaGetSymbolAddress((void**)&p_attn, g_attn);
    cudaGetSymbolAddress((void**)&p_after, g_after);
    cudaGetSymbolAddress((void**)&p_yn, g_yn);
    cudaGetSymbolAddress((void**)&p_hidden, g_hidden);
    cudaGetSymbolAddress((void**)&p_hg, g_hg);
    cudaGetSymbolAddress((void**)&p_wqkv, g_wqkv_t);
    cudaGetSymbolAddress((void**)&p_wout, g_wout_t);
    cudaGetSymbolAddress((void**)&p_win, g_win_t);
    cudaGetSymbolAddress((void**)&p_whid, g_whid_t);
    cudaGetSymbolAddress((void**)&p_wgate, g_wgate_t);

    const int SMEM_NT = 3 * (256 * 36 + 128 * 36) * 4;   // 165888
    const int SMEM_NN = 3 * (256 * 36 + 32 * 136) * 4;   // 162816
    cudaFuncSetAttribute(gemm_tc<true, false, true>,
        cudaFuncAttributeMaxDynamicSharedMemorySize, SMEM_NT);
    cudaFuncSetAttribute(gemm_tc<true, false, false>,
        cudaFuncAttributeMaxDynamicSharedMemorySize, SMEM_NT);
    cudaFuncSetAttribute(gemm_tc<false, true, true>,
        cudaFuncAttributeMaxDynamicSharedMemorySize, SMEM_NN);

    const long sQb = (long)LL * QKVN;  // batch stride inside qkv
    const long sSb = (long)HH * LL * LL;
    const long sSh = (long)LL * LL;
    const float iscale = 0.08838834764831845f;  // 1/sqrt(128)

    // 0) weight pre-conversion to tf32 bit patterns
    {
        int n4q = (QKVN * DD) / 4, n4 = (DD * DD) / 4;
        cvt_tf32_kernel<<<(n4q + 255) / 256, 256>>>(w_qkv, p_wqkv, n4q);
        cvt_tf32_kernel<<<(n4 + 255) / 256, 256>>>(w_out, p_wout, n4);
        cvt_tf32_kernel<<<(n4 + 255) / 256, 256>>>(w_in, p_win, n4);
        cvt_tf32_kernel<<<(n4 + 255) / 256, 256>>>(w_hid, p_whid, n4);
        cvt_tf32_kernel<<<(n4 + 255) / 256, 256>>>(w_gate, p_wgate, n4);
    }

    // 1) attn-branch RMSNorm (output tf32-rounded)
    rmsnorm_kernel<<<TT, 256>>>(x, g_attng, p_xn);

    // 2) QKV GEMM: [4096,2048] x [6144,2048]^T  (output rounded: feeds S/PV)
    gemm_tc<true, false, true><<<dim3(QKVN / 128, TT / 256, 1), 256, SMEM_NT>>>(
        p_xn, p_wqkv, p_qkv, DD, DD, DD, QKVN,
        1, 0, 0, 0, 0, 0, 0, 1.0f, nullptr, nullptr, 0);

    // 3) S = Q K^T / sqrt(HD), per (b,h): M=N=2048, K=128 (fp32 out: scores)
    gemm_tc<true, false, false><<<dim3(LL / 128, LL / 256, BB * HH), 256, SMEM_NT>>>(
        p_qkv, p_qkv + DD, scores, HD, QKVN, QKVN, LL,
        HH, sQb, HD, sQb, HD, sSb, sSh, iscale, nullptr, nullptr, 0);

    // 4) row softmax on scores (in place; checked output stays fp32)
    softmax_kernel<<<BB * HH * LL, 256>>>(scores);

    // 5) attn = P V, per (b,h): M=2048, N=128, K=2048 (NN; cvt A in loop)
    gemm_tc<false, true, true><<<dim3(1, LL / 256, BB * HH), 256, SMEM_NN>>>(
        scores, p_qkv + 2 * DD, p_attn, LL, LL, QKVN, DD,
        HH, sSb, sSh, sQb, HD, (long)LL * DD, HD, 1.0f, nullptr, nullptr, 0);

    // 6) after_attn = x + attn * w_out^T  (fp32 out: residual)
    gemm_tc<true, false, false><<<dim3(DD / 128, TT / 256, 1), 256, SMEM_NT>>>(
        p_attn, p_wout, p_after, DD, DD, DD, DD,
        1, 0, 0, 0, 0, 0, 0, 1.0f, nullptr, x, 0);

    // 7) FFN-branch RMSNorm (output tf32-rounded)
    rmsnorm_kernel<<<TT, 256>>>(p_after, g_ffng, p_yn);

    // 8) hidden = relu(yn * w_in^T)  (rounded: feeds GEMM 9)
    gemm_tc<true, false, true><<<dim3(DD / 128, TT / 256, 1), 256, SMEM_NT>>>(
        p_yn, p_win, p_hidden, DD, DD, DD, DD,
        1, 0, 0, 0, 0, 0, 0, 1.0f, nullptr, nullptr, 1);

    // 9) hg = hidden * (hidden * w_gate^T)  (rounded: feeds GEMM 10)
    gemm_tc<true, false, true><<<dim3(DD / 128, TT / 256, 1), 256, SMEM_NT>>>(
        p_hidden, p_wgate, p_hg, DD, DD, DD, DD,
        1, 0, 0, 0, 0, 0, 0, 1.0f, p_hidden, nullptr, 0);

    // 10) out = after_attn + hg * w_hidden^T  (fp32 final output)
    gemm_tc<true, false, false><<<dim3(DD / 128, TT / 256, 1), 256, SMEM_NT>>>(
        p_hg, p_whid, out, DD, DD, DD, DD,
        1, 0, 0, 0, 0, 0, 0, 1.0f, nullptr, p_after, 0);
}

// round 9
// speedup vs baseline: 1.9308x; 1.9308x over previous
#include <cuda_runtime.h>
#include <cuda_fp16.h>
#include <cstdint>

// Problem constants
#define BB 2
#define LL 2048
#define DD 2048
#define HH 16
#define HD 128
#define TT (BB*LL)            // 4096 tokens
#define QKVN (3*DD)           // 6144
#define OUT_ELEMS ((long)TT*DD)          // 8388608
#define SCORE_ELEMS ((long)BB*HH*LL*LL)  // 134217728

// Scratch (device globals; no allocation allowed)
__device__ __half g_xn[TT*DD];
__device__ __half g_qkv[TT*QKVN];
__device__ __half g_attn[TT*DD];
__device__ float  g_after[TT*DD];          // residual stays fp32
__device__ __half g_yn[TT*DD];
__device__ __half g_hidden[TT*DD];
__device__ __half g_hg[TT*DD];
__device__ __half g_ph[SCORE_ELEMS];       // half copy of softmax P for PV
// fp16 weight copies
__device__ __half g_wqkv_h[(long)QKVN*DD];
__device__ __half g_wout_h[(long)DD*DD];
__device__ __half g_win_h[(long)DD*DD];
__device__ __half g_whid_h[(long)DD*DD];
__device__ __half g_wgate_h[(long)DD*DD];

// ---------------------------------------------------------------------------
// Weight pre-conversion: fp32 -> fp16
// ---------------------------------------------------------------------------
__global__ void cvt_h_kernel(const float* __restrict__ src,
                             __half* __restrict__ dst, int n4) {
    int i = blockIdx.x * blockDim.x + threadIdx.x;
    if (i < n4) {
        float4 v = ((const float4*)src)[i];
        __half2 h0 = __floats2half2_rn(v.x, v.y);
        __half2 h1 = __floats2half2_rn(v.z, v.w);
        uint2 u;
        u.x = *(uint32_t*)&h0; u.y = *(uint32_t*)&h1;
        ((uint2*)dst)[i] = u;
    }
}

// ---------------------------------------------------------------------------
// Block reductions (256 threads = 8 warps)
// ---------------------------------------------------------------------------
__device__ __forceinline__ float block_reduce_max(float v, float* red) {
    int lane = threadIdx.x & 31, wid = threadIdx.x >> 5;
    #pragma unroll
    for (int o = 16; o; o >>= 1) v = fmaxf(v, __shfl_xor_sync(0xffffffffu, v, o));
    if (lane == 0) red[wid] = v;
    __syncthreads();
    if (wid == 0) {
        float u = (lane < 8) ? red[lane] : -3.4e38f;
        #pragma unroll
        for (int o = 4; o; o >>= 1) u = fmaxf(u, __shfl_xor_sync(0xffffffffu, u, o));
        if (lane == 0) red[0] = u;
    }
    __syncthreads();
    float r = red[0];
    __syncthreads();
    return r;
}

__device__ __forceinline__ float block_reduce_sum(float v, float* red) {
    int lane = threadIdx.x & 31, wid = threadIdx.x >> 5;
    #pragma unroll
    for (int o = 16; o; o >>= 1) v += __shfl_xor_sync(0xffffffffu, v, o);
    if (lane == 0) red[wid] = v;
    __syncthreads();
    if (wid == 0) {
        float u = (lane < 8) ? red[lane] : 0.f;
        #pragma unroll
        for (int o = 4; o; o >>= 1) u += __shfl_xor_sync(0xffffffffu, u, o);
        if (lane == 0) red[0] = u;
    }
    __syncthreads();
    float r = red[0];
    __syncthreads();
    return r;
}

// ---------------------------------------------------------------------------
// RMSNorm: one block per token row of D=2048; half output (GEMM operand)
// ---------------------------------------------------------------------------
__global__ void rmsnorm_kernel(const float* __restrict__ x,
                               const float* __restrict__ g,
                               __half* __restrict__ y) {
    __shared__ float red[32];
    long row = blockIdx.x;
    const float* xr = x + row * DD;
    __half* yr = y + row * DD;
    int tid = threadIdx.x;

    float4 v0 = *(const float4*)&xr[tid * 4];
    float4 v1 = *(const float4*)&xr[1024 + tid * 4];
    float ss = v0.x*v0.x + v0.y*v0.y + v0.z*v0.z + v0.w*v0.w
             + v1.x*v1.x + v1.y*v1.y + v1.z*v1.z + v1.w*v1.w;
    ss = block_reduce_sum(ss, red);
    float norm = rsqrtf(ss * (1.0f / DD) + 1e-6f);

    float4 g0 = *(const float4*)&g[tid * 4];
    float4 g1 = *(const float4*)&g[1024 + tid * 4];
    __half2 h0 = __floats2half2_rn(v0.x * norm * g0.x, v0.y * norm * g0.y);
    __half2 h1 = __floats2half2_rn(v0.z * norm * g0.z, v0.w * norm * g0.w);
    __half2 h2 = __floats2half2_rn(v1.x * norm * g1.x, v1.y * norm * g1.y);
    __half2 h3 = __floats2half2_rn(v1.z * norm * g1.z, v1.w * norm * g1.w);
    uint2 u0, u1;
    u0.x = *(uint32_t*)&h0; u0.y = *(uint32_t*)&h1;
    u1.x = *(uint32_t*)&h2; u1.y = *(uint32_t*)&h3;
    *(uint2*)&yr[tid * 4] = u0;
    *(uint2*)&yr[1024 + tid * 4] = u1;
}

// ---------------------------------------------------------------------------
// Row softmax over rows of length L=2048; writes fp32 (checked output)
// plus a half copy for the PV GEMM.
// ---------------------------------------------------------------------------
__global__ void softmax_kernel(float* __restrict__ S, __half* __restrict__ Ph) {
    __shared__ float red[32];
    long row = blockIdx.x;
    float* p = S + row * (long)LL;
    __half* ph = Ph + row * (long)LL;
    int tid = threadIdx.x;

    float4 v0 = *(const float4*)&p[tid * 4];
    float4 v1 = *(const float4*)&p[1024 + tid * 4];
    float m = fmaxf(fmaxf(fmaxf(v0.x, v0.y), fmaxf(v0.z, v0.w)),
                    fmaxf(fmaxf(v1.x, v1.y), fmaxf(v1.z, v1.w)));
    m = block_reduce_max(m, red);

    v0.x = __expf(v0.x - m); v0.y = __expf(v0.y - m);
    v0.z = __expf(v0.z - m); v0.w = __expf(v0.w - m);
    v1.x = __expf(v1.x - m); v1.y = __expf(v1.y - m);
    v1.z = __expf(v1.z - m); v1.w = __expf(v1.w - m);

    float s = v0.x + v0.y + v0.z + v0.w + v1.x + v1.y + v1.z + v1.w;
    s = block_reduce_sum(s, red);
    float inv = 1.0f / s;

    v0.x *= inv; v0.y *= inv; v0.z *= inv; v0.w *= inv;
    v1.x *= inv; v1.y *= inv; v1.z *= inv; v1.w *= inv;
    *(float4*)&p[tid * 4] = v0;
    *(float4*)&p[1024 + tid * 4] = v1;

    __half2 h0 = __floats2half2_rn(v0.x, v0.y);
    __half2 h1 = __floats2half2_rn(v0.z, v0.w);
    __half2 h2 = __floats2half2_rn(v1.x, v1.y);
    __half2 h3 = __floats2half2_rn(v1.z, v1.w);
    uint2 u0, u1;
    u0.x = *(uint32_t*)&h0; u0.y = *(uint32_t*)&h1;
    u1.x = *(uint32_t*)&h2; u1.y = *(uint32_t*)&h3;
    *(uint2*)&ph[tid * 4] = u0;
    *(uint2*)&ph[1024 + tid * 4] = u1;
}

// ---------------------------------------------------------------------------
// FP16 tensor-core GEMM (mma.sync.m16n8k16), fp32 accumulate.
//   TB=true : C = epi( A[M,K] * W[N,K]^T )   (NT, both K-major)
//   TB=false: C = epi( A[M,K] * B[K,N] )     (NN; B frags via ldmatrix.trans)
// CTA tile 128x128xBK64, 256 threads = 8 warps (2x4), warp tile 64x32.
// Double-buffered cp.async; ldmatrix.x4 fragment loads.
// OUTF: fp32 output (scores / residual / final); else half output.
// ---------------------------------------------------------------------------
__device__ __forceinline__ void cp16(__half* smem_dst, const __half* gmem_src) {
    uint32_t d = (uint32_t)__cvta_generic_to_shared(smem_dst);
    asm volatile("cp.async.cg.shared.global [%0], [%1], 16;\n"
                 :: "r"(d), "l"(gmem_src));
}

__device__ __forceinline__ void ldsm_x4(uint32_t& r0, uint32_t& r1,
                                        uint32_t& r2, uint32_t& r3,
                                        const __half* p) {
    uint32_t a = (uint32_t)__cvta_generic_to_shared(p);
    asm volatile("ldmatrix.sync.aligned.m8n8.x4.shared.b16 {%0,%1,%2,%3}, [%4];"
                 : "=r"(r0), "=r"(r1), "=r"(r2), "=r"(r3) : "r"(a));
}

__device__ __forceinline__ void ldsm_x4t(uint32_t& r0, uint32_t& r1,
                                         uint32_t& r2, uint32_t& r3,
                                         const __half* p) {
    uint32_t a = (uint32_t)__cvta_generic_to_shared(p);
    asm volatile("ldmatrix.sync.aligned.m8n8.x4.trans.shared.b16 {%0,%1,%2,%3}, [%4];"
                 : "=r"(r0), "=r"(r1), "=r"(r2), "=r"(r3) : "r"(a));
}

__device__ __forceinline__ void mma_f16(float* c, uint32_t a0, uint32_t a1,
                                        uint32_t a2, uint32_t a3,
                                        uint32_t b0, uint32_t b1) {
    asm volatile(
        "mma.sync.aligned.m16n8k16.row.col.f32.f16.f16.f32 "
        "{%0,%1,%2,%3}, {%4,%5,%6,%7}, {%8,%9}, {%0,%1,%2,%3};"
        : "+f"(c[0]), "+f"(c[1]), "+f"(c[2]), "+f"(c[3])
        : "r"(a0), "r"(a1), "r"(a2), "r"(a3), "r"(b0), "r"(b1));
}

template<bool TB, bool OUTF>
__global__ __launch_bounds__(256, 2)
void gemm_h(const __half* __restrict__ A, const __half* __restrict__ Bm,
            void* __restrict__ Cv,
            int K, int lda, int ldb, int ldc,
            int zH,
            long sAb, long sAh, long sBb, long sBh, long sCb, long sCh,
            float scale,
            const __half* __restrict__ mulp,
            const float* __restrict__ addp,
            int relu) {
    constexpr int BK = 64;
    constexpr int PA = 72;                    // halves per A/B-NT row (pad)
    constexpr int ASZ = 128 * PA;             // 9216 halves per buffer
    constexpr int PBNN = 136;                 // halves per B-NN k-row (pad)
    constexpr int BSZ = TB ? 128 * PA : BK * PBNN;

    extern __shared__ __half smem[];
    __half* As = smem;                 // 2 buffers
    __half* Bs = smem + 2 * ASZ;       // 2 buffers

    int z = blockIdx.z;
    int zb = z / zH, zh = z % zH;
    A  += zb * sAb + zh * sAh;
    Bm += zb * sBb + zh * sBh;
    const __half* mp = mulp ? (mulp + zb * sCb + zh * sCh) : nullptr;
    const float* ap = addp ? (addp + zb * sCb + zh * sCh) : nullptr;
    long cofs = zb * sCb + zh * sCh;

    int tid = threadIdx.x;
    int lane = tid & 31, warp = tid >> 5;
    int wm = warp >> 2;         // 0..1
    int wn = warp & 3;          // 0..3
    int g = lane >> 2, tig = lane & 3;
    int m_base = wm * 64, n_base = wn * 32;
    int row0 = blockIdx.y * 128;
    int col0 = blockIdx.x * 128;

    // ldmatrix lane address components
    int a_r = ((lane >> 3) & 1) * 8 + (lane & 7);   // A: row sel
    int a_c = ((lane >> 4) & 1) * 8;                // A: k sel
    int bnt_r = ((lane >> 4) & 1) * 8 + (lane & 7); // B-NT: n-row sel
    int bnt_c = ((lane >> 3) & 1) * 8;              // B-NT: k sel
    // B-NN (trans): k-row sel = bnt... same bit split as A rows over k
    int bnn_r = ((lane >> 3) & 1) * 8 + (lane & 7); // k-row
    int bnn_c = ((lane >> 4) & 1) * 8;              // n sel

    float acc[4][4][4];
    #pragma unroll
    for (int mi = 0; mi < 4; mi++)
        #pragma unroll
        for (int ni = 0; ni < 4; ni++)
            #pragma unroll
            for (int r = 0; r < 4; r++) acc[mi][ni][r] = 0.f;

    auto issue_tile = [&](int k0, int buf) {
        __half* Ab = As + buf * ASZ;
        #pragma unroll
        for (int t = 0; t < 4; t++) {
            int q = tid + t * 256;
            int r = q >> 3;            // 0..127 (m)
            int kc = (q & 7) * 8;      // 0..56
            cp16(&Ab[r * PA + kc], &A[(long)(row0 + r) * lda + k0 + kc]);
        }
        __half* Bb = Bs + buf * BSZ;
        if (TB) {
            #pragma unroll
            for (int t = 0; t < 4; t++) {
                int q = tid + t * 256;
                int r = q >> 3;
                int kc = (q & 7) * 8;
                cp16(&Bb[r * PA + kc], &Bm[(long)(col0 + r) * ldb + k0 + kc]);
            }
        } else {
            #pragma unroll
            for (int t = 0; t < 4; t++) {
                int q = tid + t * 256;
                int r = q >> 4;            // k row 0..63
                int c = (q & 15) * 8;      // col 0..120
                cp16(&Bb[r * PBNN + c], &Bm[(long)(k0 + r) * ldb + col0 + c]);
            }
        }
        asm volatile("cp.async.commit_group;\n" ::);
    };

    int nk = K / BK;
    issue_tile(0, 0);

    for (int i = 0; i < nk; i++) {
        if (i + 1 < nk) {
            issue_tile((i + 1) * BK, (i + 1) & 1);
            asm volatile("cp.async.wait_group 1;\n" ::);
        } else {
            asm volatile("cp.async.wait_group 0;\n" ::);
        }
        __syncthreads();

        const __half* Ab = As + (i & 1) * ASZ;
        const __half* Bb = Bs + (i & 1) * BSZ;

        #pragma unroll
        for (int kk = 0; kk < BK; kk += 16) {
            uint32_t af[4][4], bf[4][2];
            #pragma unroll
            for (int mi = 0; mi < 4; mi++) {
                const __half* p = Ab + (m_base + mi * 16 + a_r) * PA + kk + a_c;
                ldsm_x4(af[mi][0], af[mi][1], af[mi][2], af[mi][3], p);
            }
            if (TB) {
                #pragma unroll
                for (int p2 = 0; p2 < 2; p2++) {
                    const __half* p = Bb + (n_base + p2 * 16 + bnt_r) * PA + kk + bnt_c;
                    ldsm_x4(bf[2 * p2][0], bf[2 * p2][1],
                            bf[2 * p2 + 1][0], bf[2 * p2 + 1][1], p);
                }
            } else {
                #pragma unroll
                for (int p2 = 0; p2 < 2; p2++) {
                    const __half* p = Bb + (kk + bnn_r) * PBNN + n_base + p2 * 16 + bnn_c;
                    ldsm_x4t(bf[2 * p2][0], bf[2 * p2][1],
                             bf[2 * p2 + 1][0], bf[2 * p2 + 1][1], p);
                }
            }
            #pragma unroll
            for (int mi = 0; mi < 4; mi++)
                #pragma unroll
                for (int ni = 0; ni < 4; ni++)
                    mma_f16(acc[mi][ni], af[mi][0], af[mi][1], af[mi][2],
                            af[mi][3], bf[ni][0], bf[ni][1]);
        }
        __syncthreads();
    }

    // --- epilogue ---
    float* Cf = (float*)Cv + cofs;
    __half* Ch = (__half*)Cv + cofs;
    #pragma unroll
    for (int mi = 0; mi < 4; mi++) {
        #pragma unroll
        for (int half_i = 0; half_i < 2; half_i++) {
            int r = row0 + m_base + mi * 16 + g + half_i * 8;
            #pragma unroll
            for (int ni = 0; ni < 4; ni++) {
                int c = col0 + n_base + ni * 8 + tig * 2;
                long idx = (long)r * ldc + c;
                float2 v;
                v.x = acc[mi][ni][half_i * 2 + 0] * scale;
                v.y = acc[mi][ni][half_i * 2 + 1] * scale;
                if (mp) {
                    __half2 m2 = *(const __half2*)&mp[idx];
                    float2 mf = __half22float2(m2);
                    v.x *= mf.x; v.y *= mf.y;
                }
                if (relu) { v.x = fmaxf(v.x, 0.f); v.y = fmaxf(v.y, 0.f); }
                if (ap) {
                    float2 a2 = *(const float2*)&ap[idx];
                    v.x += a2.x; v.y += a2.y;
                }
                if (OUTF) {
                    *(float2*)&Cf[idx] = v;
                } else {
                    *(__half2*)&Ch[idx] = __floats2half2_rn(v.x, v.y);
                }
            }
        }
    }
}

// ---------------------------------------------------------------------------
extern "C" void kernel_launch(void* const* d_in, const int* in_sizes, int n_in,
                              void* d_out, int out_size) {
    (void)in_sizes; (void)n_in; (void)out_size;
    const float* x       = (const float*)d_in[0];
    const float* w_qkv   = (const float*)d_in[1];
    const float* w_out   = (const float*)d_in[2];
    const float* w_in    = (const float*)d_in[3];
    const float* w_hid   = (const float*)d_in[4];
    const float* w_gate  = (const float*)d_in[5];
    const float* g_attng = (const float*)d_in[6];
    const float* g_ffng  = (const float*)d_in[7];
    float* out = (float*)d_out;
    float* scores = out + OUT_ELEMS;

    __half *p_xn, *p_qkv, *p_attn, *p_yn, *p_hidden, *p_hg, *p_ph;
    float *p_after;
    __half *p_wqkv, *p_wout, *p_win, *p_whid, *p_wgate;
    cudaGetSymbolAddress((void**)&p_xn, g_xn);
    cudaGetSymbolAddress((void**)&p_qkv, g_qkv);
    cudaGetSymbolAddress((void**)&p_attn, g_attn);
    cudaGetSymbolAddress((void**)&p_after, g_after);
    cudaGetSymbolAddress((void**)&p_yn, g_yn);
    cudaGetSymbolAddress((void**)&p_hidden, g_hidden);
    cudaGetSymbolAddress((void**)&p_hg, g_hg);
    cudaGetSymbolAddress((void**)&p_ph, g_ph);
    cudaGetSymbolAddress((void**)&p_wqkv, g_wqkv_h);
    cudaGetSymbolAddress((void**)&p_wout, g_wout_h);
    cudaGetSymbolAddress((void**)&p_win, g_win_h);
    cudaGetSymbolAddress((void**)&p_whid, g_whid_h);
    cudaGetSymbolAddress((void**)&p_wgate, g_wgate_h);

    const int SMEM_NT = (2 * 128 * 72 + 2 * 128 * 72) * 2;   // 73728 B
    const int SMEM_NN = (2 * 128 * 72 + 2 * 64 * 136) * 2;   // 71680 B
    cudaFuncSetAttribute(gemm_h<true, false>,
        cudaFuncAttributeMaxDynamicSharedMemorySize, SMEM_NT);
    cudaFuncSetAttribute(gemm_h<true, true>,
        cudaFuncAttributeMaxDynamicSharedMemorySize, SMEM_NT);
    cudaFuncSetAttribute(gemm_h<false, false>,
        cudaFuncAttributeMaxDynamicSharedMemorySize, SMEM_NN);

    const long sQb = (long)LL * QKVN;  // batch stride inside qkv
    const long sSb = (long)HH * LL * LL;
    const long sSh = (long)LL * LL;
    const float iscale = 0.08838834764831845f;  // 1/sqrt(128)

    // 0) weight pre-conversion to fp16
    {
        int n4q = (QKVN * DD) / 4, n4 = (DD * DD) / 4;
        cvt_h_kernel<<<(n4q + 255) / 256, 256>>>(w_qkv, p_wqkv, n4q);
        cvt_h_kernel<<<(n4 + 255) / 256, 256>>>(w_out, p_wout, n4);
        cvt_h_kernel<<<(n4 + 255) / 256, 256>>>(w_in, p_win, n4);
        cvt_h_kernel<<<(n4 + 255) / 256, 256>>>(w_hid, p_whid, n4);
        cvt_h_kernel<<<(n4 + 255) / 256, 256>>>(w_gate, p_wgate, n4);
    }

    // 1) attn-branch RMSNorm (half output)
    rmsnorm_kernel<<<TT, 256>>>(x, g_attng, p_xn);

    // 2) QKV GEMM: [4096,2048] x [6144,2048]^T  (half out)
    gemm_h<true, false><<<dim3(QKVN / 128, TT / 128, 1), 256, SMEM_NT>>>(
        p_xn, p_wqkv, p_qkv, DD, DD, DD, QKVN,
        1, 0, 0, 0, 0, 0, 0, 1.0f, nullptr, nullptr, 0);

    // 3) S = Q K^T / sqrt(HD), per (b,h): M=N=2048, K=128 (fp32 out: scores)
    gemm_h<true, true><<<dim3(LL / 128, LL / 128, BB * HH), 256, SMEM_NT>>>(
        p_qkv, p_qkv + DD, scores, HD, QKVN, QKVN, LL,
        HH, sQb, HD, sQb, HD, sSb, sSh, iscale, nullptr, nullptr, 0);

    // 4) row softmax on scores (fp32 output + half copy for PV)
    softmax_kernel<<<BB * HH * LL, 256>>>(scores, p_ph);

    // 5) attn = P V, per (b,h): M=2048, N=128, K=2048 (NN; half out)
    gemm_h<false, false><<<dim3(1, LL / 128, BB * HH), 256, SMEM_NN>>>(
        p_ph, p_qkv + 2 * DD, p_attn, LL, LL, QKVN, DD,
        HH, sSb, sSh, sQb, HD, (long)LL * DD, HD, 1.0f, nullptr, nullptr, 0);

    // 6) after_attn = x + attn * w_out^T  (fp32 out: residual)
    gemm_h<true, true><<<dim3(DD / 128, TT / 128, 1), 256, SMEM_NT>>>(
        p_attn, p_wout, p_after, DD, DD, DD, DD,
        1, 0, 0, 0, 0, 0, 0, 1.0f, nullptr, x, 0);

    // 7) FFN-branch RMSNorm (half output)
    rmsnorm_kernel<<<TT, 256>>>(p_after, g_ffng, p_yn);

    // 8) hidden = relu(yn * w_in^T)  (half out)
    gemm_h<true, false><<<dim3(DD / 128, TT / 128, 1), 256, SMEM_NT>>>(
        p_yn, p_win, p_hidden, DD, DD, DD, DD,
        1, 0, 0, 0, 0, 0, 0, 1.0f, nullptr, nullptr, 1);

    // 9) hg = hidden * (hidden * w_gate^T)  (half out)
    gemm_h<true, false><<<dim3(DD / 128, TT / 128, 1), 256, SMEM_NT>>>(
        p_hidden, p_wgate, p_hg, DD, DD, DD, DD,
        1, 0, 0, 0, 0, 0, 0, 1.0f, p_hidden, nullptr, 0);

    // 10) out = after_attn + hg * w_hidden^T  (fp32 final output)
    gemm_h<true, true><<<dim3(DD / 128, TT / 128, 1), 256, SMEM_NT>>>(
        p_hg, p_whid, out, DD, DD, DD, DD,
        1, 0, 0, 0, 0, 0, 0, 1.0f, nullptr, p_after, 0);
}